// round 1
// baseline (speedup 1.0000x reference)
#include <cuda_runtime.h>
#include <math.h>

#define NMAX 50000
#define EMAX 800000
#define KD 256
#define OD 128

// ---------------- scratch (device globals: no allocs allowed) ----------------
__device__ float g_hp[(size_t)NMAX * OD];   // h' = X @ W   [N,128]
__device__ float g_edst[NMAX];
__device__ float g_esrc[NMAX];
__device__ int   g_cnt[NMAX];
__device__ int   g_off[NMAX + 1];
__device__ int   g_cur[NMAX];
__device__ int   g_ssrc[EMAX];              // edge src sorted by dst
__device__ float g_sscore[EMAX];            // leaky-relu'd score sorted by dst

// ---------------- GEMM: [M,256] x [256,128] -> [M,128], fp32 ----------------
// BM=128, BN=128, BK=16, 256 threads, 8x8 per thread.
__global__ __launch_bounds__(256, 2)
void k_gemm(const float* __restrict__ A, const float* __restrict__ W,
            float* __restrict__ C, int M) {
    __shared__ float As[128][16];
    __shared__ float Bs[16][128];
    const int tid = threadIdx.x;
    const int m0 = blockIdx.x * 128;
    const int row_c = tid >> 4;   // 0..15
    const int col_c = tid & 15;   // 0..15

    float acc[8][8];
#pragma unroll
    for (int i = 0; i < 8; i++)
#pragma unroll
        for (int j = 0; j < 8; j++) acc[i][j] = 0.f;

    for (int k0 = 0; k0 < KD; k0 += 16) {
        // load A tile: 128 rows x 16 k = 512 float4, 2 per thread
#pragma unroll
        for (int t = 0; t < 2; t++) {
            int idx = tid + t * 256;          // 0..511
            int r = idx >> 2;                 // 0..127
            int c4 = idx & 3;                 // float4 index within 16 k
            int gr = m0 + r;
            float4 v = make_float4(0.f, 0.f, 0.f, 0.f);
            if (gr < M) v = *(const float4*)(A + (size_t)gr * KD + k0 + c4 * 4);
            As[r][c4 * 4 + 0] = v.x;
            As[r][c4 * 4 + 1] = v.y;
            As[r][c4 * 4 + 2] = v.z;
            As[r][c4 * 4 + 3] = v.w;
            // load W tile: 16 rows x 128 = 512 float4
            int rb = idx >> 5;                // 0..15
            int cb = (idx & 31) * 4;          // 0..124
            *(float4*)&Bs[rb][cb] = *(const float4*)(W + (size_t)(k0 + rb) * OD + cb);
        }
        __syncthreads();
#pragma unroll
        for (int k = 0; k < 16; k++) {
            float a[8], b[8];
#pragma unroll
            for (int i = 0; i < 8; i++) a[i] = As[row_c * 8 + i][k];
            float4 b0 = *(float4*)&Bs[k][col_c * 8];
            float4 b1 = *(float4*)&Bs[k][col_c * 8 + 4];
            b[0] = b0.x; b[1] = b0.y; b[2] = b0.z; b[3] = b0.w;
            b[4] = b1.x; b[5] = b1.y; b[6] = b1.z; b[7] = b1.w;
#pragma unroll
            for (int i = 0; i < 8; i++)
#pragma unroll
                for (int j = 0; j < 8; j++)
                    acc[i][j] = fmaf(a[i], b[j], acc[i][j]);
        }
        __syncthreads();
    }
#pragma unroll
    for (int i = 0; i < 8; i++) {
        int r = m0 + row_c * 8 + i;
        if (r < M) {
            float4 v0 = make_float4(acc[i][0], acc[i][1], acc[i][2], acc[i][3]);
            float4 v1 = make_float4(acc[i][4], acc[i][5], acc[i][6], acc[i][7]);
            *(float4*)(C + (size_t)r * OD + col_c * 8) = v0;
            *(float4*)(C + (size_t)r * OD + col_c * 8 + 4) = v1;
        }
    }
}

// ---------------- per-node attention logits: e = h'.a + b ----------------
__global__ void k_node_e(const float* __restrict__ hp,
                         const float* __restrict__ a_dst, const float* __restrict__ b_dst,
                         const float* __restrict__ a_src, const float* __restrict__ b_src,
                         float* __restrict__ edst, float* __restrict__ esrc, int n) {
    int warp = (blockIdx.x * blockDim.x + threadIdx.x) >> 5;
    int lane = threadIdx.x & 31;
    if (warp >= n) return;
    float4 h = *(const float4*)(hp + (size_t)warp * OD + lane * 4);
    float4 ad = *(const float4*)(a_dst + lane * 4);
    float4 as = *(const float4*)(a_src + lane * 4);
    float sd = h.x * ad.x + h.y * ad.y + h.z * ad.z + h.w * ad.w;
    float ss = h.x * as.x + h.y * as.y + h.z * as.z + h.w * as.w;
#pragma unroll
    for (int d = 16; d; d >>= 1) {
        sd += __shfl_xor_sync(0xffffffffu, sd, d);
        ss += __shfl_xor_sync(0xffffffffu, ss, d);
    }
    if (lane == 0) {
        edst[warp] = sd + b_dst[0];
        esrc[warp] = ss + b_src[0];
    }
}

// ---------------- CSR build ----------------
__global__ void k_zero(int* __restrict__ cnt, int n) {
    int i = blockIdx.x * blockDim.x + threadIdx.x;
    if (i < n) cnt[i] = 0;
}

__global__ void k_count(const int* __restrict__ dst, int e, int* __restrict__ cnt) {
    int i = blockIdx.x * blockDim.x + threadIdx.x;
    if (i < e) atomicAdd(&cnt[dst[i]], 1);
}

// single-block exclusive scan over cnt[0..n) -> off, cur; off[n] = total
__global__ __launch_bounds__(1024)
void k_scan(const int* __restrict__ cnt, int n, int* __restrict__ off, int* __restrict__ cur) {
    __shared__ int warp_sums[32];
    __shared__ int s_carry;
    int tid = threadIdx.x;
    if (tid == 0) s_carry = 0;
    __syncthreads();
    for (int base = 0; base < n; base += 1024) {
        int i = base + tid;
        int v = (i < n) ? cnt[i] : 0;
        int x = v;
#pragma unroll
        for (int d = 1; d < 32; d <<= 1) {
            int y = __shfl_up_sync(0xffffffffu, x, d);
            if ((tid & 31) >= d) x += y;
        }
        if ((tid & 31) == 31) warp_sums[tid >> 5] = x;
        __syncthreads();
        if (tid < 32) {
            int w = warp_sums[tid];
#pragma unroll
            for (int d = 1; d < 32; d <<= 1) {
                int y = __shfl_up_sync(0xffffffffu, w, d);
                if (tid >= d) w += y;
            }
            warp_sums[tid] = w;  // inclusive over warp sums
        }
        __syncthreads();
        int warp_prefix = (tid >= 32) ? warp_sums[(tid >> 5) - 1] : 0;
        int incl = x + warp_prefix;
        int excl = incl - v;
        int carry = s_carry;
        if (i < n) {
            off[i] = carry + excl;
            cur[i] = carry + excl;
        }
        __syncthreads();
        if (tid == 1023) s_carry = carry + incl;  // incl of last thread = tile total
        __syncthreads();
    }
    if (tid == 0) off[n] = s_carry;
}

__global__ void k_scatter(const int* __restrict__ src, const int* __restrict__ dst, int e,
                          int* __restrict__ cur,
                          const float* __restrict__ edst, const float* __restrict__ esrc,
                          int* __restrict__ ssrc, float* __restrict__ sscore) {
    int i = blockIdx.x * blockDim.x + threadIdx.x;
    if (i >= e) return;
    int d = dst[i], s = src[i];
    int p = atomicAdd(&cur[d], 1);
    float sc = edst[d] + esrc[s];
    ssrc[p] = s;
    sscore[p] = (sc >= 0.f) ? sc : 0.2f * sc;
}

// ---------------- warp-per-dst softmax + weighted aggregation + ELU ----------------
__global__ __launch_bounds__(256)
void k_agg(const int* __restrict__ off, const int* __restrict__ ssrc,
           const float* __restrict__ sscore, const float* __restrict__ hp,
           const float* __restrict__ bias, float* __restrict__ out, int n) {
    int warp = (blockIdx.x * blockDim.x + threadIdx.x) >> 5;
    int lane = threadIdx.x & 31;
    if (warp >= n) return;
    int s = off[warp], e = off[warp + 1];

    float m = -INFINITY;
    for (int i = s + lane; i < e; i += 32) m = fmaxf(m, sscore[i]);
#pragma unroll
    for (int d = 16; d; d >>= 1) m = fmaxf(m, __shfl_xor_sync(0xffffffffu, m, d));

    float sum = 0.f;
    for (int i = s + lane; i < e; i += 32) sum += __expf(sscore[i] - m);
#pragma unroll
    for (int d = 16; d; d >>= 1) sum += __shfl_xor_sync(0xffffffffu, sum, d);
    float inv = 1.0f / fmaxf(sum, 1e-12f);

    float4 acc = make_float4(0.f, 0.f, 0.f, 0.f);
    int i = s;
    // unroll-by-2 for memory-level parallelism
    for (; i + 1 < e; i += 2) {
        int s0 = ssrc[i], s1 = ssrc[i + 1];
        float w0 = __expf(sscore[i] - m) * inv;
        float w1 = __expf(sscore[i + 1] - m) * inv;
        float4 h0 = *(const float4*)(hp + (size_t)s0 * OD + lane * 4);
        float4 h1 = *(const float4*)(hp + (size_t)s1 * OD + lane * 4);
        acc.x += w0 * h0.x + w1 * h1.x;
        acc.y += w0 * h0.y + w1 * h1.y;
        acc.z += w0 * h0.z + w1 * h1.z;
        acc.w += w0 * h0.w + w1 * h1.w;
    }
    if (i < e) {
        int s0 = ssrc[i];
        float w0 = __expf(sscore[i] - m) * inv;
        float4 h0 = *(const float4*)(hp + (size_t)s0 * OD + lane * 4);
        acc.x += w0 * h0.x; acc.y += w0 * h0.y; acc.z += w0 * h0.z; acc.w += w0 * h0.w;
    }

    float4 b = *(const float4*)(bias + lane * 4);
    acc.x += b.x; acc.y += b.y; acc.z += b.z; acc.w += b.w;
    // ELU
    acc.x = acc.x > 0.f ? acc.x : expm1f(acc.x);
    acc.y = acc.y > 0.f ? acc.y : expm1f(acc.y);
    acc.z = acc.z > 0.f ? acc.z : expm1f(acc.z);
    acc.w = acc.w > 0.f ? acc.w : expm1f(acc.w);
    *(float4*)(out + (size_t)warp * OD + lane * 4) = acc;
}

// ---------------- launch ----------------
extern "C" void kernel_launch(void* const* d_in, const int* in_sizes, int n_in,
                              void* d_out, int out_size) {
    const float* inputs = (const float*)d_in[0];
    const int*   esrc   = (const int*)d_in[1];
    const int*   edst   = (const int*)d_in[2];
    const float* W      = (const float*)d_in[3];
    const float* a_dst  = (const float*)d_in[4];
    const float* b_dst  = (const float*)d_in[5];
    const float* a_src  = (const float*)d_in[6];
    const float* b_src  = (const float*)d_in[7];
    const float* obias  = (const float*)d_in[8];
    float* out = (float*)d_out;

    int n = in_sizes[0] / KD;
    int e = in_sizes[1];

    float *hp, *pedst, *pesrc, *pscore;
    int *pcnt, *poff, *pcur, *pssrc;
    cudaGetSymbolAddress((void**)&hp, g_hp);
    cudaGetSymbolAddress((void**)&pedst, g_edst);
    cudaGetSymbolAddress((void**)&pesrc, g_esrc);
    cudaGetSymbolAddress((void**)&pcnt, g_cnt);
    cudaGetSymbolAddress((void**)&poff, g_off);
    cudaGetSymbolAddress((void**)&pcur, g_cur);
    cudaGetSymbolAddress((void**)&pssrc, g_ssrc);
    cudaGetSymbolAddress((void**)&pscore, g_sscore);

    k_gemm<<<(n + 127) / 128, 256>>>(inputs, W, hp, n);
    k_node_e<<<(n * 32 + 255) / 256, 256>>>(hp, a_dst, b_dst, a_src, b_src, pedst, pesrc, n);
    k_zero<<<(n + 255) / 256, 256>>>(pcnt, n);
    k_count<<<(e + 255) / 256, 256>>>(edst, e, pcnt);
    k_scan<<<1, 1024>>>(pcnt, n, poff, pcur);
    k_scatter<<<(e + 255) / 256, 256>>>(esrc, edst, e, pcur, pedst, pesrc, pssrc, pscore);
    k_agg<<<(n * 32 + 255) / 256, 256>>>(poff, pssrc, pscore, hp, obias, out, n);
}

// round 3
// speedup vs baseline: 1.4473x; 1.4473x over previous
#include <cuda_runtime.h>
#include <math.h>
#include <stdint.h>

#define NMAX 50000
#define EMAX 800000
#define KD 256
#define OD 128

// ---------------- scratch (device globals: no allocs allowed) ----------------
__device__ float g_hp[(size_t)NMAX * OD];   // h' = X @ W   [N,128]
__device__ float g_edst[NMAX];
__device__ float g_esrc[NMAX];
__device__ int   g_cnt[NMAX];
__device__ int   g_off[NMAX + 1];
__device__ int   g_cur[NMAX];
__device__ int   g_ssrc[EMAX];              // edge src sorted by dst
__device__ float g_sscore[EMAX];            // leaky-relu'd score sorted by dst
__device__ int   g_bsum[256];
__device__ int   g_bpre[256];

// ---------------- tf32 helpers ----------------
__device__ __forceinline__ float f2tf32(float x) {
    uint32_t u;
    asm("cvt.rna.tf32.f32 %0, %1;" : "=r"(u) : "f"(x));
    return __uint_as_float(u);
}

__device__ __forceinline__ void mma_tf32(float* d, const uint32_t* a, const uint32_t* b) {
    asm volatile(
        "mma.sync.aligned.m16n8k8.row.col.f32.tf32.tf32.f32 "
        "{%0,%1,%2,%3}, {%4,%5,%6,%7}, {%8,%9}, {%0,%1,%2,%3};"
        : "+f"(d[0]), "+f"(d[1]), "+f"(d[2]), "+f"(d[3])
        : "r"(a[0]), "r"(a[1]), "r"(a[2]), "r"(a[3]), "r"(b[0]), "r"(b[1]));
}

// ---------------- GEMM: [M,256] x [256,128] -> [M,128], 3xTF32 tensor core ----------------
// BM=128, BN=128(full), BK=16. 256 threads = 8 warps in 4x2; warp tile 32x64.
#define APAD 20    // As row stride (floats): conflict-free frag reads
#define BPAD 136   // Bs row stride (floats): conflict-free frag reads

__global__ __launch_bounds__(256, 2)
void k_gemm(const float* __restrict__ A, const float* __restrict__ W,
            float* __restrict__ C, int M) {
    __shared__ float As_hi[128 * APAD];
    __shared__ float As_lo[128 * APAD];
    __shared__ float Bs_hi[16 * BPAD];
    __shared__ float Bs_lo[16 * BPAD];

    const int tid  = threadIdx.x;
    const int lane = tid & 31;
    const int warp = tid >> 5;
    const int wm = warp >> 1;        // 0..3
    const int wn = warp & 1;         // 0..1
    const int m0 = blockIdx.x * 128;
    const int g = lane >> 2;         // 0..7
    const int t = lane & 3;          // 0..3

    float acc[2][8][4];
#pragma unroll
    for (int mt = 0; mt < 2; mt++)
#pragma unroll
        for (int nt = 0; nt < 8; nt++)
#pragma unroll
            for (int c = 0; c < 4; c++) acc[mt][nt][c] = 0.f;

    // per-thread global-load coordinates (2 float4 of A, 2 of B per BK tile)
    int a_r[2], a_c[2], b_r[2], b_c[2];
#pragma unroll
    for (int s = 0; s < 2; s++) {
        int idx = tid + s * 256;         // 0..511
        a_r[s] = idx >> 2;               // 0..127
        a_c[s] = (idx & 3) * 4;          // 0,4,8,12
        b_r[s] = idx >> 5;               // 0..15
        b_c[s] = (idx & 31) * 4;         // 0..124
    }

    float4 pa[2], pb[2];
    // prefetch tile kt=0
#pragma unroll
    for (int s = 0; s < 2; s++) {
        int gr = m0 + a_r[s];
        pa[s] = (gr < M) ? *(const float4*)(A + (size_t)gr * KD + a_c[s])
                         : make_float4(0.f, 0.f, 0.f, 0.f);
        pb[s] = *(const float4*)(W + (size_t)b_r[s] * OD + b_c[s]);
    }

    for (int kt = 0; kt < 16; kt++) {
        // stage prefetched tile into smem with hi/lo tf32 split
#pragma unroll
        for (int s = 0; s < 2; s++) {
            float4 v = pa[s];
            float4 hi, lo;
            hi.x = f2tf32(v.x); lo.x = f2tf32(v.x - hi.x);
            hi.y = f2tf32(v.y); lo.y = f2tf32(v.y - hi.y);
            hi.z = f2tf32(v.z); lo.z = f2tf32(v.z - hi.z);
            hi.w = f2tf32(v.w); lo.w = f2tf32(v.w - hi.w);
            *(float4*)&As_hi[a_r[s] * APAD + a_c[s]] = hi;
            *(float4*)&As_lo[a_r[s] * APAD + a_c[s]] = lo;
            v = pb[s];
            hi.x = f2tf32(v.x); lo.x = f2tf32(v.x - hi.x);
            hi.y = f2tf32(v.y); lo.y = f2tf32(v.y - hi.y);
            hi.z = f2tf32(v.z); lo.z = f2tf32(v.z - hi.z);
            hi.w = f2tf32(v.w); lo.w = f2tf32(v.w - hi.w);
            *(float4*)&Bs_hi[b_r[s] * BPAD + b_c[s]] = hi;
            *(float4*)&Bs_lo[b_r[s] * BPAD + b_c[s]] = lo;
        }
        __syncthreads();

        // prefetch next tile (overlap LDG with mma)
        if (kt < 15) {
            int k0 = (kt + 1) * 16;
#pragma unroll
            for (int s = 0; s < 2; s++) {
                int gr = m0 + a_r[s];
                pa[s] = (gr < M) ? *(const float4*)(A + (size_t)gr * KD + k0 + a_c[s])
                                 : make_float4(0.f, 0.f, 0.f, 0.f);
                pb[s] = *(const float4*)(W + (size_t)(k0 + b_r[s]) * OD + b_c[s]);
            }
        }

        // compute: 2 k-steps of k8
#pragma unroll
        for (int ks = 0; ks < 2; ks++) {
            int ko = ks * 8;
            uint32_t ah[2][4], al[2][4];
#pragma unroll
            for (int mt = 0; mt < 2; mt++) {
                int rm = wm * 32 + mt * 16;
                ah[mt][0] = __float_as_uint(As_hi[(rm + g) * APAD + ko + t]);
                ah[mt][1] = __float_as_uint(As_hi[(rm + g + 8) * APAD + ko + t]);
                ah[mt][2] = __float_as_uint(As_hi[(rm + g) * APAD + ko + t + 4]);
                ah[mt][3] = __float_as_uint(As_hi[(rm + g + 8) * APAD + ko + t + 4]);
                al[mt][0] = __float_as_uint(As_lo[(rm + g) * APAD + ko + t]);
                al[mt][1] = __float_as_uint(As_lo[(rm + g + 8) * APAD + ko + t]);
                al[mt][2] = __float_as_uint(As_lo[(rm + g) * APAD + ko + t + 4]);
                al[mt][3] = __float_as_uint(As_lo[(rm + g + 8) * APAD + ko + t + 4]);
            }
#pragma unroll
            for (int nt = 0; nt < 8; nt++) {
                int nc = wn * 64 + nt * 8 + g;
                uint32_t bh[2], bl[2];
                bh[0] = __float_as_uint(Bs_hi[(ko + t) * BPAD + nc]);
                bh[1] = __float_as_uint(Bs_hi[(ko + t + 4) * BPAD + nc]);
                bl[0] = __float_as_uint(Bs_lo[(ko + t) * BPAD + nc]);
                bl[1] = __float_as_uint(Bs_lo[(ko + t + 4) * BPAD + nc]);
#pragma unroll
                for (int mt = 0; mt < 2; mt++) {
                    mma_tf32(acc[mt][nt], ah[mt], bh);   // hi*hi
                    mma_tf32(acc[mt][nt], al[mt], bh);   // lo*hi
                    mma_tf32(acc[mt][nt], ah[mt], bl);   // hi*lo
                }
            }
        }
        __syncthreads();
    }

    // epilogue: c0=(g,2t) c1=(g,2t+1) c2=(g+8,2t) c3=(g+8,2t+1)
#pragma unroll
    for (int mt = 0; mt < 2; mt++) {
#pragma unroll
        for (int nt = 0; nt < 8; nt++) {
            int row = m0 + wm * 32 + mt * 16 + g;
            int col = wn * 64 + nt * 8 + 2 * t;
            if (row < M)
                *(float2*)(C + (size_t)row * OD + col) = make_float2(acc[mt][nt][0], acc[mt][nt][1]);
            if (row + 8 < M)
                *(float2*)(C + (size_t)(row + 8) * OD + col) = make_float2(acc[mt][nt][2], acc[mt][nt][3]);
        }
    }
}

// ---------------- per-node attention logits: e = h'.a + b ----------------
__global__ void k_node_e(const float* __restrict__ hp,
                         const float* __restrict__ a_dst, const float* __restrict__ b_dst,
                         const float* __restrict__ a_src, const float* __restrict__ b_src,
                         float* __restrict__ edst, float* __restrict__ esrc, int n) {
    int warp = (blockIdx.x * blockDim.x + threadIdx.x) >> 5;
    int lane = threadIdx.x & 31;
    if (warp >= n) return;
    float4 h = *(const float4*)(hp + (size_t)warp * OD + lane * 4);
    float4 ad = *(const float4*)(a_dst + lane * 4);
    float4 as = *(const float4*)(a_src + lane * 4);
    float sd = h.x * ad.x + h.y * ad.y + h.z * ad.z + h.w * ad.w;
    float ss = h.x * as.x + h.y * as.y + h.z * as.z + h.w * as.w;
#pragma unroll
    for (int d = 16; d; d >>= 1) {
        sd += __shfl_xor_sync(0xffffffffu, sd, d);
        ss += __shfl_xor_sync(0xffffffffu, ss, d);
    }
    if (lane == 0) {
        edst[warp] = sd + b_dst[0];
        esrc[warp] = ss + b_src[0];
    }
}

// ---------------- CSR build ----------------
__global__ void k_zero(int* __restrict__ cnt, int n) {
    int i = blockIdx.x * blockDim.x + threadIdx.x;
    if (i < n) cnt[i] = 0;
}

__global__ void k_count(const int* __restrict__ dst, int e, int* __restrict__ cnt) {
    int i = (blockIdx.x * blockDim.x + threadIdx.x) * 4;
    if (i + 3 < e) {
        int4 d = *(const int4*)(dst + i);
        atomicAdd(&cnt[d.x], 1);
        atomicAdd(&cnt[d.y], 1);
        atomicAdd(&cnt[d.z], 1);
        atomicAdd(&cnt[d.w], 1);
    } else {
        for (int j = i; j < e; j++) atomicAdd(&cnt[dst[j]], 1);
    }
}

// ---- hierarchical exclusive scan: scan1 (per 256-block) -> scan2 (block sums) -> scan3 (add) ----
__global__ __launch_bounds__(256)
void k_scan1(const int* __restrict__ cnt, int n, int* __restrict__ off) {
    __shared__ int ws[8];
    int tid = threadIdx.x, lane = tid & 31, w = tid >> 5;
    int i = blockIdx.x * 256 + tid;
    int v = (i < n) ? cnt[i] : 0;
    int x = v;
#pragma unroll
    for (int d = 1; d < 32; d <<= 1) {
        int y = __shfl_up_sync(0xffffffffu, x, d);
        if (lane >= d) x += y;
    }
    if (lane == 31) ws[w] = x;
    __syncthreads();
    if (tid < 8) {
        int s = ws[tid];
#pragma unroll
        for (int d = 1; d < 8; d <<= 1) {
            int y = __shfl_up_sync(0xffu, s, d);
            if (tid >= d) s += y;
        }
        ws[tid] = s;
    }
    __syncthreads();
    int incl = x + (w ? ws[w - 1] : 0);
    if (i < n) off[i] = incl - v;             // block-local exclusive
    if (tid == 255) g_bsum[blockIdx.x] = incl; // block total
}

__global__ __launch_bounds__(256)
void k_scan2(int nb, int n, int* __restrict__ off) {
    __shared__ int ws[8];
    int tid = threadIdx.x, lane = tid & 31, w = tid >> 5;
    int v = (tid < nb) ? g_bsum[tid] : 0;
    int x = v;
#pragma unroll
    for (int d = 1; d < 32; d <<= 1) {
        int y = __shfl_up_sync(0xffffffffu, x, d);
        if (lane >= d) x += y;
    }
    if (lane == 31) ws[w] = x;
    __syncthreads();
    if (tid < 8) {
        int s = ws[tid];
#pragma unroll
        for (int d = 1; d < 8; d <<= 1) {
            int y = __shfl_up_sync(0xffu, s, d);
            if (tid >= d) s += y;
        }
        ws[tid] = s;
    }
    __syncthreads();
    int incl = x + (w ? ws[w - 1] : 0);
    g_bpre[tid] = incl - v;                  // exclusive prefix of block sums
    if (tid == 255) off[n] = incl;           // grand total
}

__global__ void k_scan3(int n, int* __restrict__ off, int* __restrict__ cur) {
    int i = blockIdx.x * 256 + threadIdx.x;
    if (i < n) {
        int o = off[i] + g_bpre[blockIdx.x];
        off[i] = o;
        cur[i] = o;
    }
}

__global__ void k_scatter(const int* __restrict__ src, const int* __restrict__ dst, int e,
                          int* __restrict__ cur,
                          const float* __restrict__ edst, const float* __restrict__ esrc,
                          int* __restrict__ ssrc, float* __restrict__ sscore) {
    int i = blockIdx.x * blockDim.x + threadIdx.x;
    if (i >= e) return;
    int d = dst[i], s = src[i];
    int p = atomicAdd(&cur[d], 1);
    float sc = edst[d] + esrc[s];
    ssrc[p] = s;
    sscore[p] = (sc >= 0.f) ? sc : 0.2f * sc;
}

// ---------------- warp-per-dst softmax + weighted aggregation + ELU ----------------
__global__ __launch_bounds__(256)
void k_agg(const int* __restrict__ off, const int* __restrict__ ssrc,
           const float* __restrict__ sscore, const float* __restrict__ hp,
           const float* __restrict__ bias, float* __restrict__ out, int n) {
    int warp = (blockIdx.x * blockDim.x + threadIdx.x) >> 5;
    int lane = threadIdx.x & 31;
    if (warp >= n) return;
    int s = off[warp], e = off[warp + 1];

    float m = -INFINITY;
    for (int i = s + lane; i < e; i += 32) m = fmaxf(m, sscore[i]);
#pragma unroll
    for (int d = 16; d; d >>= 1) m = fmaxf(m, __shfl_xor_sync(0xffffffffu, m, d));

    float sum = 0.f;
    for (int i = s + lane; i < e; i += 32) sum += __expf(sscore[i] - m);
#pragma unroll
    for (int d = 16; d; d >>= 1) sum += __shfl_xor_sync(0xffffffffu, sum, d);
    float inv = 1.0f / fmaxf(sum, 1e-12f);

    float4 acc = make_float4(0.f, 0.f, 0.f, 0.f);
    int i = s;
    for (; i + 1 < e; i += 2) {
        int s0 = ssrc[i], s1 = ssrc[i + 1];
        float w0 = __expf(sscore[i] - m) * inv;
        float w1 = __expf(sscore[i + 1] - m) * inv;
        float4 h0 = *(const float4*)(hp + (size_t)s0 * OD + lane * 4);
        float4 h1 = *(const float4*)(hp + (size_t)s1 * OD + lane * 4);
        acc.x += w0 * h0.x + w1 * h1.x;
        acc.y += w0 * h0.y + w1 * h1.y;
        acc.z += w0 * h0.z + w1 * h1.z;
        acc.w += w0 * h0.w + w1 * h1.w;
    }
    if (i < e) {
        int s0 = ssrc[i];
        float w0 = __expf(sscore[i] - m) * inv;
        float4 h0 = *(const float4*)(hp + (size_t)s0 * OD + lane * 4);
        acc.x += w0 * h0.x; acc.y += w0 * h0.y; acc.z += w0 * h0.z; acc.w += w0 * h0.w;
    }

    float4 b = *(const float4*)(bias + lane * 4);
    acc.x += b.x; acc.y += b.y; acc.z += b.z; acc.w += b.w;
    acc.x = acc.x > 0.f ? acc.x : expm1f(acc.x);
    acc.y = acc.y > 0.f ? acc.y : expm1f(acc.y);
    acc.z = acc.z > 0.f ? acc.z : expm1f(acc.z);
    acc.w = acc.w > 0.f ? acc.w : expm1f(acc.w);
    *(float4*)(out + (size_t)warp * OD + lane * 4) = acc;
}

// ---------------- launch ----------------
extern "C" void kernel_launch(void* const* d_in, const int* in_sizes, int n_in,
                              void* d_out, int out_size) {
    const float* inputs = (const float*)d_in[0];
    const int*   esrc   = (const int*)d_in[1];
    const int*   edst   = (const int*)d_in[2];
    const float* W      = (const float*)d_in[3];
    const float* a_dst  = (const float*)d_in[4];
    const float* b_dst  = (const float*)d_in[5];
    const float* a_src  = (const float*)d_in[6];
    const float* b_src  = (const float*)d_in[7];
    const float* obias  = (const float*)d_in[8];
    float* out = (float*)d_out;

    int n = in_sizes[0] / KD;
    int e = in_sizes[1];
    int nb = (n + 255) / 256;

    float *hp, *pedst, *pesrc, *pscore;
    int *pcnt, *poff, *pcur, *pssrc;
    cudaGetSymbolAddress((void**)&hp, g_hp);
    cudaGetSymbolAddress((void**)&pedst, g_edst);
    cudaGetSymbolAddress((void**)&pesrc, g_esrc);
    cudaGetSymbolAddress((void**)&pcnt, g_cnt);
    cudaGetSymbolAddress((void**)&poff, g_off);
    cudaGetSymbolAddress((void**)&pcur, g_cur);
    cudaGetSymbolAddress((void**)&pssrc, g_ssrc);
    cudaGetSymbolAddress((void**)&pscore, g_sscore);

    k_gemm<<<(n + 127) / 128, 256>>>(inputs, W, hp, n);
    k_node_e<<<(n * 32 + 255) / 256, 256>>>(hp, a_dst, b_dst, a_src, b_src, pedst, pesrc, n);
    k_zero<<<(n + 255) / 256, 256>>>(pcnt, n);
    k_count<<<((e + 3) / 4 + 255) / 256, 256>>>(edst, e, pcnt);
    k_scan1<<<nb, 256>>>(pcnt, n, poff);
    k_scan2<<<1, 256>>>(nb, n, poff);
    k_scan3<<<nb, 256>>>(n, poff, pcur);
    k_scatter<<<(e + 255) / 256, 256>>>(esrc, edst, e, pcur, pedst, pesrc, pssrc, pscore);
    k_agg<<<(n * 32 + 255) / 256, 256>>>(poff, pssrc, pscore, hp, obias, out, n);
}